// round 1
// baseline (speedup 1.0000x reference)
#include <cuda_runtime.h>
#include <math.h>

// Problem constants
#define NB   2
#define NN   50000
#define NE   800000
#define INPD 128
#define NKEY 64
#define NVAL 128
#define M_ROWS (NB * NN)   // 100000 flattened (b, n) rows

// ---------------- scratch (device globals; no allocation allowed) ----------
__device__ float d_values[(size_t)M_ROWS * NVAL];  // [b][n][v]
__device__ float d_agg[(size_t)M_ROWS * NVAL];     // [b][n][v]
__device__ float d_ksum[M_ROWS];                   // [b][n]
__device__ float d_kwsum[INPD];
__device__ float d_kbsum;
__device__ int   d_cnt[NN];
__device__ int   d_cnt2[NN];
__device__ int   d_offs[NN + 1];
__device__ int   d_perm[NE];

// ---------------- prep: kw row-sums, kb sum ----------------
__global__ void prep_k(const float* __restrict__ k_w, const float* __restrict__ k_b) {
    int i = threadIdx.x;
    if (i < INPD) {
        float s = 0.f;
        #pragma unroll
        for (int j = 0; j < NKEY; j++) s += k_w[i * NKEY + j];
        d_kwsum[i] = s;
    }
    if (i == 0) {
        float b = 0.f;
        #pragma unroll
        for (int j = 0; j < NKEY; j++) b += k_b[j];
        d_kbsum = b;
    }
}

__global__ void zero_cnt_k() {
    int i = blockIdx.x * blockDim.x + threadIdx.x;
    if (i < NN) { d_cnt[i] = 0; d_cnt2[i] = 0; }
}

__global__ void hist_k(const int* __restrict__ rows) {
    int e = blockIdx.x * blockDim.x + threadIdx.x;
    if (e < NE) atomicAdd(&d_cnt[rows[e]], 1);
}

// single-block exclusive scan over d_cnt -> d_offs
__global__ void scan_k() {
    __shared__ int wsum[32];
    int tid = threadIdx.x, lane = tid & 31, wid = tid >> 5;
    int carry = 0;
    for (int base = 0; base < NN; base += 1024) {
        int i = base + tid;
        int v = (i < NN) ? d_cnt[i] : 0;
        int x = v;
        #pragma unroll
        for (int d = 1; d < 32; d <<= 1) {
            int t = __shfl_up_sync(0xffffffffu, x, d);
            if (lane >= d) x += t;
        }
        if (lane == 31) wsum[wid] = x;
        __syncthreads();
        if (wid == 0) {
            int s = wsum[lane];
            #pragma unroll
            for (int d = 1; d < 32; d <<= 1) {
                int t = __shfl_up_sync(0xffffffffu, s, d);
                if (lane >= d) s += t;
            }
            wsum[lane] = s;
        }
        __syncthreads();
        int pre  = (wid > 0) ? wsum[wid - 1] : 0;
        int incl = x + pre;
        if (i < NN) d_offs[i] = carry + incl - v;
        int total = wsum[31];
        __syncthreads();
        carry += total;
    }
    if (tid == 0) d_offs[NN] = carry;
}

__global__ void scatter_k(const int* __restrict__ rows) {
    int e = blockIdx.x * blockDim.x + threadIdx.x;
    if (e < NE) {
        int r = rows[e];
        int p = d_offs[r] + atomicAdd(&d_cnt2[r], 1);
        d_perm[p] = e;
    }
}

// ---------------- GEMM A: values = x @ v_w + v_b ; ksum = x . kwsum + kbsum --
// Tile: 32 rows x 128 cols, K=128 in chunks of 32; 256 threads; warp tr owns
// rows tr*4..tr*4+3, lane owns cols lane*4..lane*4+3.
__global__ __launch_bounds__(256) void gemm_values_k(
    const float* __restrict__ x, const float* __restrict__ v_w,
    const float* __restrict__ v_b)
{
    __shared__ float Ws[32][NVAL];
    __shared__ float As[32][33];
    __shared__ float Ks[32];
    int tid = threadIdx.x;
    int tr = tid >> 5, lane = tid & 31;
    size_t row0 = (size_t)blockIdx.x * 32;

    float acc[4][4];
    #pragma unroll
    for (int r = 0; r < 4; r++)
        #pragma unroll
        for (int c = 0; c < 4; c++) acc[r][c] = 0.f;
    float ksp[4] = {0.f, 0.f, 0.f, 0.f};

    for (int kc = 0; kc < INPD; kc += 32) {
        for (int l = tid; l < 32 * NVAL; l += 256) {
            int k = l >> 7, c = l & 127;
            Ws[k][c] = v_w[(size_t)(kc + k) * NVAL + c];
        }
        for (int l = tid; l < 32 * 32; l += 256) {
            int r = l >> 5, k = l & 31;
            As[r][k] = x[(row0 + r) * INPD + kc + k];
        }
        if (tid < 32) Ks[tid] = d_kwsum[kc + tid];
        __syncthreads();

        #pragma unroll
        for (int kk = 0; kk < 32; kk++) {
            float4 w = *(const float4*)&Ws[kk][lane * 4];
            #pragma unroll
            for (int rr = 0; rr < 4; rr++) {
                float a = As[tr * 4 + rr][kk];
                acc[rr][0] += a * w.x; acc[rr][1] += a * w.y;
                acc[rr][2] += a * w.z; acc[rr][3] += a * w.w;
            }
        }
        #pragma unroll
        for (int rr = 0; rr < 4; rr++)
            ksp[rr] += As[tr * 4 + rr][lane] * Ks[lane];
        __syncthreads();
    }

    float4 vb = *(const float4*)&v_b[lane * 4];
    #pragma unroll
    for (int rr = 0; rr < 4; rr++) {
        float4 o;
        o.x = acc[rr][0] + vb.x; o.y = acc[rr][1] + vb.y;
        o.z = acc[rr][2] + vb.z; o.w = acc[rr][3] + vb.w;
        *(float4*)&d_values[(row0 + tr * 4 + rr) * NVAL + lane * 4] = o;
    }
    #pragma unroll
    for (int rr = 0; rr < 4; rr++) {
        float s = ksp[rr];
        #pragma unroll
        for (int off = 16; off; off >>= 1) s += __shfl_xor_sync(0xffffffffu, s, off);
        if (lane == 0) d_ksum[row0 + tr * 4 + rr] = s + d_kbsum;
    }
}

// ---------------- Edge kernel: per-row softmax + weighted gather-sum -------
__global__ __launch_bounds__(256) void edge_k(
    const int* __restrict__ cols_, const float* __restrict__ conn)
{
    int gw = (blockIdx.x * 256 + threadIdx.x) >> 5;
    int lane = threadIdx.x & 31;
    if (gw >= NN) return;
    int n = gw;
    int beg = d_offs[n], end = d_offs[n + 1];
    float* a0 = &d_agg[(size_t)n * NVAL];
    float* a1 = &d_agg[((size_t)NN + n) * NVAL];
    if (beg == end) {
        float4 z = {0.f, 0.f, 0.f, 0.f};
        *(float4*)&a0[lane * 4] = z;
        *(float4*)&a1[lane * 4] = z;
        return;
    }
    const float* ks0 = d_ksum;
    const float* ks1 = d_ksum + NN;

    // pass 1: per-lane online softmax stats for both batches
    float m0 = -1e30f, dd0 = 0.f, m1 = -1e30f, dd1 = 0.f;
    for (int i = beg + lane; i < end; i += 32) {
        int e = d_perm[i];
        float cv = conn[e];
        int c = cols_[e];
        float s0 = cv * ks0[c], s1 = cv * ks1[c];
        if (s0 > m0) { dd0 = dd0 * expf(m0 - s0) + 1.f; m0 = s0; }
        else         { dd0 += expf(s0 - m0); }
        if (s1 > m1) { dd1 = dd1 * expf(m1 - s1) + 1.f; m1 = s1; }
        else         { dd1 += expf(s1 - m1); }
    }
    // warp combine
    #pragma unroll
    for (int off = 16; off; off >>= 1) {
        float om = __shfl_xor_sync(0xffffffffu, m0, off);
        float od = __shfl_xor_sync(0xffffffffu, dd0, off);
        float nm = fmaxf(m0, om);
        dd0 = dd0 * expf(m0 - nm) + od * expf(om - nm);
        m0 = nm;
        om = __shfl_xor_sync(0xffffffffu, m1, off);
        od = __shfl_xor_sync(0xffffffffu, dd1, off);
        nm = fmaxf(m1, om);
        dd1 = dd1 * expf(m1 - nm) + od * expf(om - nm);
        m1 = nm;
    }
    float inv0 = 1.f / dd0;
    float inv1 = 1.f / dd1;

    // pass 2: weighted accumulate of values rows (128 floats / warp)
    float4 acc0 = {0.f, 0.f, 0.f, 0.f};
    float4 acc1 = {0.f, 0.f, 0.f, 0.f};
    const float* v0b = d_values;
    const float* v1b = d_values + (size_t)NN * NVAL;
    for (int base = beg; base < end; base += 32) {
        int i = base + lane;
        float w0 = 0.f, w1 = 0.f;
        int c = 0;
        if (i < end) {
            int e = d_perm[i];
            float cv = conn[e];
            c = cols_[e];
            w0 = expf(cv * ks0[c] - m0) * inv0;
            w1 = expf(cv * ks1[c] - m1) * inv1;
        }
        int cnt = min(32, end - base);
        for (int j = 0; j < cnt; j++) {
            float wj0 = __shfl_sync(0xffffffffu, w0, j);
            float wj1 = __shfl_sync(0xffffffffu, w1, j);
            int   cj  = __shfl_sync(0xffffffffu, c, j);
            float4 v0 = *(const float4*)&v0b[(size_t)cj * NVAL + lane * 4];
            float4 v1 = *(const float4*)&v1b[(size_t)cj * NVAL + lane * 4];
            acc0.x += wj0 * v0.x; acc0.y += wj0 * v0.y;
            acc0.z += wj0 * v0.z; acc0.w += wj0 * v0.w;
            acc1.x += wj1 * v1.x; acc1.y += wj1 * v1.y;
            acc1.z += wj1 * v1.z; acc1.w += wj1 * v1.w;
        }
    }
    *(float4*)&a0[lane * 4] = acc0;
    *(float4*)&a1[lane * 4] = acc1;
}

// ---------------- GEMM C: h = agg @ out_w + out_b ; silu; layernorm --------
__global__ __launch_bounds__(256) void gemm_out_k(
    const float* __restrict__ ow, const float* __restrict__ ob,
    const float* __restrict__ lng, const float* __restrict__ lnb,
    float* __restrict__ out)
{
    __shared__ float Ws[32][NVAL];
    __shared__ float As[32][33];
    __shared__ __align__(16) float Hs[32][132];  // 132*4=528B row stride, 16B-aligned
    int tid = threadIdx.x;
    int tr = tid >> 5, lane = tid & 31;
    size_t row0 = (size_t)blockIdx.x * 32;

    float acc[4][4];
    #pragma unroll
    for (int r = 0; r < 4; r++)
        #pragma unroll
        for (int c = 0; c < 4; c++) acc[r][c] = 0.f;

    for (int kc = 0; kc < NVAL; kc += 32) {
        for (int l = tid; l < 32 * NVAL; l += 256) {
            int k = l >> 7, c = l & 127;
            Ws[k][c] = ow[(size_t)(kc + k) * NVAL + c];
        }
        for (int l = tid; l < 32 * 32; l += 256) {
            int r = l >> 5, k = l & 31;
            As[r][k] = d_agg[(row0 + r) * NVAL + kc + k];
        }
        __syncthreads();
        #pragma unroll
        for (int kk = 0; kk < 32; kk++) {
            float4 w = *(const float4*)&Ws[kk][lane * 4];
            #pragma unroll
            for (int rr = 0; rr < 4; rr++) {
                float a = As[tr * 4 + rr][kk];
                acc[rr][0] += a * w.x; acc[rr][1] += a * w.y;
                acc[rr][2] += a * w.z; acc[rr][3] += a * w.w;
            }
        }
        __syncthreads();
    }

    // silu into shared
    float4 b4 = *(const float4*)&ob[lane * 4];
    #pragma unroll
    for (int rr = 0; rr < 4; rr++) {
        float h0 = acc[rr][0] + b4.x, h1 = acc[rr][1] + b4.y;
        float h2 = acc[rr][2] + b4.z, h3 = acc[rr][3] + b4.w;
        h0 = h0 / (1.f + expf(-h0)); h1 = h1 / (1.f + expf(-h1));
        h2 = h2 / (1.f + expf(-h2)); h3 = h3 / (1.f + expf(-h3));
        Hs[tr * 4 + rr][lane * 4 + 0] = h0;
        Hs[tr * 4 + rr][lane * 4 + 1] = h1;
        Hs[tr * 4 + rr][lane * 4 + 2] = h2;
        Hs[tr * 4 + rr][lane * 4 + 3] = h3;
    }
    __syncthreads();

    // layernorm per row; warp tr handles rows tr*4..tr*4+3
    float4 g4 = *(const float4*)&lng[lane * 4];
    float4 bb4 = *(const float4*)&lnb[lane * 4];
    #pragma unroll
    for (int rr = 0; rr < 4; rr++) {
        int r = tr * 4 + rr;
        float4 h4 = *(const float4*)&Hs[r][lane * 4];
        float s1 = h4.x + h4.y + h4.z + h4.w;
        float s2 = h4.x * h4.x + h4.y * h4.y + h4.z * h4.z + h4.w * h4.w;
        #pragma unroll
        for (int off = 16; off; off >>= 1) {
            s1 += __shfl_xor_sync(0xffffffffu, s1, off);
            s2 += __shfl_xor_sync(0xffffffffu, s2, off);
        }
        float mu = s1 * (1.f / NVAL);
        float var = s2 * (1.f / NVAL) - mu * mu;
        float rs = rsqrtf(var + 1e-5f);
        float4 o;
        o.x = (h4.x - mu) * rs * g4.x + bb4.x;
        o.y = (h4.y - mu) * rs * g4.y + bb4.y;
        o.z = (h4.z - mu) * rs * g4.z + bb4.z;
        o.w = (h4.w - mu) * rs * g4.w + bb4.w;
        *(float4*)&out[(row0 + r) * NVAL + lane * 4] = o;
    }
}

// ---------------- launch ---------------------------------------------------
extern "C" void kernel_launch(void* const* d_in, const int* in_sizes, int n_in,
                              void* d_out, int out_size) {
    const float* x      = (const float*)d_in[0];
    const float* conn   = (const float*)d_in[1];
    const float* k_w    = (const float*)d_in[2];
    const float* k_b    = (const float*)d_in[3];
    const float* v_w    = (const float*)d_in[4];
    const float* v_b    = (const float*)d_in[5];
    const float* out_w  = (const float*)d_in[6];
    const float* out_b  = (const float*)d_in[7];
    const float* ln_g   = (const float*)d_in[8];
    const float* ln_b   = (const float*)d_in[9];
    const int*   rows   = (const int*)d_in[10];
    const int*   cols   = (const int*)d_in[11];
    float* out = (float*)d_out;

    prep_k<<<1, 128>>>(k_w, k_b);
    zero_cnt_k<<<(NN + 255) / 256, 256>>>();
    hist_k<<<(NE + 255) / 256, 256>>>(rows);
    scan_k<<<1, 1024>>>();
    scatter_k<<<(NE + 255) / 256, 256>>>(rows);
    gemm_values_k<<<M_ROWS / 32, 256>>>(x, v_w, v_b);
    edge_k<<<(NN + 7) / 8, 256>>>(cols, conn);
    gemm_out_k<<<M_ROWS / 32, 256>>>(out_w, out_b, ln_g, ln_b, out);
}

// round 2
// speedup vs baseline: 1.3999x; 1.3999x over previous
#include <cuda_runtime.h>
#include <math.h>

// Problem constants
#define NB   2
#define NN   50000
#define NE   800000
#define INPD 128
#define NKEY 64
#define NVAL 128
#define M_ROWS (NB * NN)   // 100000 flattened (b, n) rows
#define SCAN_BLK 1024
#define SCAN_NBLK ((NN + SCAN_BLK - 1) / SCAN_BLK)   // 49

// ---------------- scratch (device globals; no allocation allowed) ----------
__device__ float d_values[(size_t)M_ROWS * NVAL];  // [b][n][v]
__device__ float d_agg[(size_t)M_ROWS * NVAL];     // [b][n][v]
__device__ float d_ksum[M_ROWS];                   // [b][n]
__device__ float d_kwsum[INPD];
__device__ float d_kbsum;
__device__ int    d_cnt[NN];
__device__ int    d_cnt2[NN];
__device__ int    d_offs[NN + 1];
__device__ int    d_bsum[SCAN_NBLK];
__device__ int    d_bsumex[SCAN_NBLK];
__device__ float2 d_score[NE];   // CSR-ordered (score_b0, score_b1)
__device__ int    d_ecol[NE];    // CSR-ordered sender col

// ---------------- prep: kw row-sums, kb sum ----------------
__global__ void prep_k(const float* __restrict__ k_w, const float* __restrict__ k_b) {
    int i = threadIdx.x;
    if (i < INPD) {
        float s = 0.f;
        #pragma unroll
        for (int j = 0; j < NKEY; j++) s += k_w[i * NKEY + j];
        d_kwsum[i] = s;
    }
    if (i == 0) {
        float b = 0.f;
        #pragma unroll
        for (int j = 0; j < NKEY; j++) b += k_b[j];
        d_kbsum = b;
    }
}

__global__ void zero_cnt_k() {
    int i = blockIdx.x * blockDim.x + threadIdx.x;
    if (i < NN) { d_cnt[i] = 0; d_cnt2[i] = 0; }
}

__global__ void hist_k(const int* __restrict__ rows) {
    int e = blockIdx.x * blockDim.x + threadIdx.x;
    if (e < NE) atomicAdd(&d_cnt[rows[e]], 1);
}

// ---------------- 3-phase parallel scan ----------------
__global__ __launch_bounds__(SCAN_BLK) void scan1_k() {
    __shared__ int wsum[32];
    int tid = threadIdx.x, lane = tid & 31, wid = tid >> 5;
    int i = blockIdx.x * SCAN_BLK + tid;
    int v = (i < NN) ? d_cnt[i] : 0;
    int x = v;
    #pragma unroll
    for (int d = 1; d < 32; d <<= 1) {
        int t = __shfl_up_sync(0xffffffffu, x, d);
        if (lane >= d) x += t;
    }
    if (lane == 31) wsum[wid] = x;
    __syncthreads();
    if (wid == 0) {
        int s = wsum[lane];
        #pragma unroll
        for (int d = 1; d < 32; d <<= 1) {
            int t = __shfl_up_sync(0xffffffffu, s, d);
            if (lane >= d) s += t;
        }
        wsum[lane] = s;
    }
    __syncthreads();
    int pre = (wid > 0) ? wsum[wid - 1] : 0;
    if (i < NN) d_offs[i] = pre + x - v;           // block-local exclusive
    if (tid == SCAN_BLK - 1) d_bsum[blockIdx.x] = pre + x;
}

__global__ void scan2_k() {
    if (threadIdx.x == 0) {
        int acc = 0;
        #pragma unroll
        for (int b = 0; b < SCAN_NBLK; b++) {
            int t = d_bsum[b];
            d_bsumex[b] = acc;
            acc += t;
        }
        d_offs[NN] = acc;
    }
}

__global__ void scan3_k() {
    int i = blockIdx.x * blockDim.x + threadIdx.x;
    if (i < NN) d_offs[i] += d_bsumex[i >> 10];
}

// scatter: CSR-order scores + cols (ksum must be ready)
__global__ void scatter_k(const int* __restrict__ rows, const int* __restrict__ cols_,
                          const float* __restrict__ conn) {
    int e = blockIdx.x * blockDim.x + threadIdx.x;
    if (e < NE) {
        int r = rows[e];
        int c = cols_[e];
        float cv = conn[e];
        int p = d_offs[r] + atomicAdd(&d_cnt2[r], 1);
        d_score[p] = make_float2(cv * d_ksum[c], cv * d_ksum[NN + c]);
        d_ecol[p] = c;
    }
}

// ---------------- GEMM A: values = x @ v_w + v_b ; ksum = x . kwsum + kbsum --
// Tile: 64 rows x 128 cols; 256 threads; warp tr owns rows tr*8..tr*8+7,
// lane owns cols lane*4..lane*4+3.
__global__ __launch_bounds__(256) void gemm_values_k(
    const float* __restrict__ x, const float* __restrict__ v_w,
    const float* __restrict__ v_b)
{
    __shared__ __align__(16) float Ws[32][NVAL];   // 16KB
    __shared__ __align__(16) float As[64][32];     // 8KB
    __shared__ float Ks[32];
    int tid = threadIdx.x;
    int tr = tid >> 5, lane = tid & 31;
    size_t row0 = (size_t)blockIdx.x * 64;

    float acc[8][4];
    #pragma unroll
    for (int r = 0; r < 8; r++)
        #pragma unroll
        for (int c = 0; c < 4; c++) acc[r][c] = 0.f;
    float ksp[8];
    #pragma unroll
    for (int r = 0; r < 8; r++) ksp[r] = 0.f;

    for (int kc = 0; kc < INPD; kc += 32) {
        // Ws: 32x128 = 1024 float4, 256 threads x 4
        #pragma unroll
        for (int q = 0; q < 4; q++) {
            int l = tid + q * 256;            // float4 index
            int k = l >> 5, c = (l & 31) * 4;
            *(float4*)&Ws[k][c] = *(const float4*)&v_w[(size_t)(kc + k) * NVAL + c];
        }
        // As: 64x32 = 512 float4, 256 threads x 2
        #pragma unroll
        for (int q = 0; q < 2; q++) {
            int l = tid + q * 256;
            int r = l >> 3, kq = (l & 7) * 4;
            size_t row = row0 + r;
            if (row >= M_ROWS) row = M_ROWS - 1;
            *(float4*)&As[r][kq] = *(const float4*)&x[row * INPD + kc + kq];
        }
        if (tid < 32) Ks[tid] = d_kwsum[kc + tid];
        __syncthreads();

        #pragma unroll
        for (int k4 = 0; k4 < 8; k4++) {
            float4 a[8];
            #pragma unroll
            for (int rr = 0; rr < 8; rr++)
                a[rr] = *(const float4*)&As[tr * 8 + rr][k4 * 4];
            #pragma unroll
            for (int kk = 0; kk < 4; kk++) {
                float4 w = *(const float4*)&Ws[k4 * 4 + kk][lane * 4];
                #pragma unroll
                for (int rr = 0; rr < 8; rr++) {
                    float av = (kk == 0) ? a[rr].x : (kk == 1) ? a[rr].y
                             : (kk == 2) ? a[rr].z : a[rr].w;
                    acc[rr][0] += av * w.x; acc[rr][1] += av * w.y;
                    acc[rr][2] += av * w.z; acc[rr][3] += av * w.w;
                }
            }
        }
        #pragma unroll
        for (int rr = 0; rr < 8; rr++)
            ksp[rr] += As[tr * 8 + rr][lane] * Ks[lane];
        __syncthreads();
    }

    float4 vb = *(const float4*)&v_b[lane * 4];
    #pragma unroll
    for (int rr = 0; rr < 8; rr++) {
        size_t row = row0 + tr * 8 + rr;
        if (row < M_ROWS) {
            float4 o;
            o.x = acc[rr][0] + vb.x; o.y = acc[rr][1] + vb.y;
            o.z = acc[rr][2] + vb.z; o.w = acc[rr][3] + vb.w;
            *(float4*)&d_values[row * NVAL + lane * 4] = o;
        }
    }
    #pragma unroll
    for (int rr = 0; rr < 8; rr++) {
        float s = ksp[rr];
        #pragma unroll
        for (int off = 16; off; off >>= 1) s += __shfl_xor_sync(0xffffffffu, s, off);
        size_t row = row0 + tr * 8 + rr;
        if (lane == 0 && row < M_ROWS) d_ksum[row] = s + d_kbsum;
    }
}

// ---------------- Edge kernel: per-row softmax + weighted gather-sum -------
__global__ __launch_bounds__(256) void edge_k() {
    int gw = (blockIdx.x * 256 + threadIdx.x) >> 5;
    int lane = threadIdx.x & 31;
    if (gw >= NN) return;
    int n = gw;
    int beg = d_offs[n], end = d_offs[n + 1];
    float* a0 = &d_agg[(size_t)n * NVAL];
    float* a1 = &d_agg[((size_t)NN + n) * NVAL];
    if (beg == end) {
        float4 z = {0.f, 0.f, 0.f, 0.f};
        *(float4*)&a0[lane * 4] = z;
        *(float4*)&a1[lane * 4] = z;
        return;
    }

    // pass 1: per-lane online softmax stats for both batches (coalesced float2)
    float m0 = -1e30f, dd0 = 0.f, m1 = -1e30f, dd1 = 0.f;
    for (int i = beg + lane; i < end; i += 32) {
        float2 s = d_score[i];
        if (s.x > m0) { dd0 = dd0 * expf(m0 - s.x) + 1.f; m0 = s.x; }
        else          { dd0 += expf(s.x - m0); }
        if (s.y > m1) { dd1 = dd1 * expf(m1 - s.y) + 1.f; m1 = s.y; }
        else          { dd1 += expf(s.y - m1); }
    }
    #pragma unroll
    for (int off = 16; off; off >>= 1) {
        float om = __shfl_xor_sync(0xffffffffu, m0, off);
        float od = __shfl_xor_sync(0xffffffffu, dd0, off);
        float nm = fmaxf(m0, om);
        dd0 = dd0 * expf(m0 - nm) + od * expf(om - nm);
        m0 = nm;
        om = __shfl_xor_sync(0xffffffffu, m1, off);
        od = __shfl_xor_sync(0xffffffffu, dd1, off);
        nm = fmaxf(m1, om);
        dd1 = dd1 * expf(m1 - nm) + od * expf(om - nm);
        m1 = nm;
    }
    float inv0 = 1.f / dd0;
    float inv1 = 1.f / dd1;

    // pass 2: weighted accumulate of values rows (128 floats / warp / batch)
    float4 acc0 = {0.f, 0.f, 0.f, 0.f};
    float4 acc1 = {0.f, 0.f, 0.f, 0.f};
    const float* v0b = d_values;
    const float* v1b = d_values + (size_t)NN * NVAL;
    for (int base = beg; base < end; base += 32) {
        int i = base + lane;
        float w0 = 0.f, w1 = 0.f;
        int c = 0;
        if (i < end) {
            float2 s = d_score[i];
            c = d_ecol[i];
            w0 = expf(s.x - m0) * inv0;
            w1 = expf(s.y - m1) * inv1;
        }
        int cnt = min(32, end - base);
        for (int j = 0; j < cnt; j++) {
            float wj0 = __shfl_sync(0xffffffffu, w0, j);
            float wj1 = __shfl_sync(0xffffffffu, w1, j);
            int   cj  = __shfl_sync(0xffffffffu, c, j);
            float4 v0 = *(const float4*)&v0b[(size_t)cj * NVAL + lane * 4];
            float4 v1 = *(const float4*)&v1b[(size_t)cj * NVAL + lane * 4];
            acc0.x += wj0 * v0.x; acc0.y += wj0 * v0.y;
            acc0.z += wj0 * v0.z; acc0.w += wj0 * v0.w;
            acc1.x += wj1 * v1.x; acc1.y += wj1 * v1.y;
            acc1.z += wj1 * v1.z; acc1.w += wj1 * v1.w;
        }
    }
    *(float4*)&a0[lane * 4] = acc0;
    *(float4*)&a1[lane * 4] = acc1;
}

// ---------------- GEMM C: h = agg @ out_w + out_b ; silu; layernorm --------
__global__ __launch_bounds__(256) void gemm_out_k(
    const float* __restrict__ ow, const float* __restrict__ ob,
    const float* __restrict__ lng, const float* __restrict__ lnb,
    float* __restrict__ out)
{
    __shared__ __align__(16) float Ws[32][NVAL];
    __shared__ __align__(16) float As[64][32];
    int tid = threadIdx.x;
    int tr = tid >> 5, lane = tid & 31;
    size_t row0 = (size_t)blockIdx.x * 64;

    float acc[8][4];
    #pragma unroll
    for (int r = 0; r < 8; r++)
        #pragma unroll
        for (int c = 0; c < 4; c++) acc[r][c] = 0.f;

    for (int kc = 0; kc < NVAL; kc += 32) {
        #pragma unroll
        for (int q = 0; q < 4; q++) {
            int l = tid + q * 256;
            int k = l >> 5, c = (l & 31) * 4;
            *(float4*)&Ws[k][c] = *(const float4*)&ow[(size_t)(kc + k) * NVAL + c];
        }
        #pragma unroll
        for (int q = 0; q < 2; q++) {
            int l = tid + q * 256;
            int r = l >> 3, kq = (l & 7) * 4;
            size_t row = row0 + r;
            if (row >= M_ROWS) row = M_ROWS - 1;
            *(float4*)&As[r][kq] = *(const float4*)&d_agg[row * NVAL + kc + kq];
        }
        __syncthreads();
        #pragma unroll
        for (int k4 = 0; k4 < 8; k4++) {
            float4 a[8];
            #pragma unroll
            for (int rr = 0; rr < 8; rr++)
                a[rr] = *(const float4*)&As[tr * 8 + rr][k4 * 4];
            #pragma unroll
            for (int kk = 0; kk < 4; kk++) {
                float4 w = *(const float4*)&Ws[k4 * 4 + kk][lane * 4];
                #pragma unroll
                for (int rr = 0; rr < 8; rr++) {
                    float av = (kk == 0) ? a[rr].x : (kk == 1) ? a[rr].y
                             : (kk == 2) ? a[rr].z : a[rr].w;
                    acc[rr][0] += av * w.x; acc[rr][1] += av * w.y;
                    acc[rr][2] += av * w.z; acc[rr][3] += av * w.w;
                }
            }
        }
        __syncthreads();
    }

    // silu + layernorm, all in registers (each warp owns complete rows)
    float4 b4 = *(const float4*)&ob[lane * 4];
    float4 g4 = *(const float4*)&lng[lane * 4];
    float4 bb4 = *(const float4*)&lnb[lane * 4];
    #pragma unroll
    for (int rr = 0; rr < 8; rr++) {
        float h0 = acc[rr][0] + b4.x, h1 = acc[rr][1] + b4.y;
        float h2 = acc[rr][2] + b4.z, h3 = acc[rr][3] + b4.w;
        h0 = h0 / (1.f + expf(-h0)); h1 = h1 / (1.f + expf(-h1));
        h2 = h2 / (1.f + expf(-h2)); h3 = h3 / (1.f + expf(-h3));
        float s1 = h0 + h1 + h2 + h3;
        float s2 = h0 * h0 + h1 * h1 + h2 * h2 + h3 * h3;
        #pragma unroll
        for (int off = 16; off; off >>= 1) {
            s1 += __shfl_xor_sync(0xffffffffu, s1, off);
            s2 += __shfl_xor_sync(0xffffffffu, s2, off);
        }
        float mu = s1 * (1.f / NVAL);
        float var = s2 * (1.f / NVAL) - mu * mu;
        float rs = rsqrtf(var + 1e-5f);
        size_t row = row0 + tr * 8 + rr;
        if (row < M_ROWS) {
            float4 o;
            o.x = (h0 - mu) * rs * g4.x + bb4.x;
            o.y = (h1 - mu) * rs * g4.y + bb4.y;
            o.z = (h2 - mu) * rs * g4.z + bb4.z;
            o.w = (h3 - mu) * rs * g4.w + bb4.w;
            *(float4*)&out[row * NVAL + lane * 4] = o;
        }
    }
}

// ---------------- launch ---------------------------------------------------
extern "C" void kernel_launch(void* const* d_in, const int* in_sizes, int n_in,
                              void* d_out, int out_size) {
    const float* x      = (const float*)d_in[0];
    const float* conn   = (const float*)d_in[1];
    const float* k_w    = (const float*)d_in[2];
    const float* k_b    = (const float*)d_in[3];
    const float* v_w    = (const float*)d_in[4];
    const float* v_b    = (const float*)d_in[5];
    const float* out_w  = (const float*)d_in[6];
    const float* out_b  = (const float*)d_in[7];
    const float* ln_g   = (const float*)d_in[8];
    const float* ln_b   = (const float*)d_in[9];
    const int*   rows   = (const int*)d_in[10];
    const int*   cols   = (const int*)d_in[11];
    float* out = (float*)d_out;

    prep_k<<<1, 128>>>(k_w, k_b);
    zero_cnt_k<<<(NN + 255) / 256, 256>>>();
    hist_k<<<(NE + 255) / 256, 256>>>(rows);
    scan1_k<<<SCAN_NBLK, SCAN_BLK>>>();
    scan2_k<<<1, 32>>>();
    scan3_k<<<(NN + 255) / 256, 256>>>();
    gemm_values_k<<<(M_ROWS + 63) / 64, 256>>>(x, v_w, v_b);
    scatter_k<<<(NE + 255) / 256, 256>>>(rows, cols, conn);
    edge_k<<<(NN + 7) / 8, 256>>>();
    gemm_out_k<<<(M_ROWS + 63) / 64, 256>>>(out_w, out_b, ln_g, ln_b, out);
}